// round 1
// baseline (speedup 1.0000x reference)
#include <cuda_runtime.h>

#define NQ   4
#define DIM  16
#define NH   8
#define NL   2
#define EMB  32
#define NT3  81   // 3^4 basis terms per head

// Per-head Fourier coefficients: layout [h][t][i]  (i = qubit/ev index, float4-friendly)
__device__ float g_C[NH * NT3 * 4];

// ---------------------------------------------------------------------------
// Setup kernel: simulate the fixed (param-only) unitary U_h on all 16 basis
// states, then expand ev_i = psi^T Re(U^dag Z_i U) psi into the 81-term
// {1, cos x_q, sin x_q} tensor basis. Grid: NH blocks x 128 threads.
// ---------------------------------------------------------------------------
__global__ void qc_setup_kernel(const float* __restrict__ params) {
    __shared__ float Vre[DIM][DIM];   // [input basis k][amplitude m]
    __shared__ float Vim[DIM][DIM];

    const int h   = blockIdx.x;
    const int tid = threadIdx.x;

    if (tid < DIM) {
        const int k = tid;
        float re[DIM], im[DIM];
        #pragma unroll
        for (int m = 0; m < DIM; m++) { re[m] = 0.f; im[m] = 0.f; }
        re[k] = 1.f;

        const float* p = params + h * NL * NQ * 3;

        for (int l = 0; l < NL; l++) {
            for (int q = 0; q < NQ; q++) {
                const int mask = 1 << (3 - q);   // qubit 0 = MSB (reference layout)
                float th, c, s;

                // RX(theta)
                th = p[(l * NQ + q) * 3 + 0];
                c = cosf(0.5f * th); s = sinf(0.5f * th);
                #pragma unroll
                for (int m = 0; m < DIM; m++) {
                    if (!(m & mask)) {
                        const int m1 = m | mask;
                        float r0 = re[m], i0 = im[m], r1 = re[m1], i1 = im[m1];
                        re[m]  = c * r0 + s * i1;
                        im[m]  = c * i0 - s * r1;
                        re[m1] = c * r1 + s * i0;
                        im[m1] = c * i1 - s * r0;
                    }
                }
                // RY(theta)
                th = p[(l * NQ + q) * 3 + 1];
                c = cosf(0.5f * th); s = sinf(0.5f * th);
                #pragma unroll
                for (int m = 0; m < DIM; m++) {
                    if (!(m & mask)) {
                        const int m1 = m | mask;
                        float r0 = re[m], i0 = im[m], r1 = re[m1], i1 = im[m1];
                        re[m]  = c * r0 - s * r1;
                        im[m]  = c * i0 - s * i1;
                        re[m1] = s * r0 + c * r1;
                        im[m1] = s * i0 + c * i1;
                    }
                }
                // RZ(theta): diag(e^{-i th/2}, e^{+i th/2})
                th = p[(l * NQ + q) * 3 + 2];
                c = cosf(0.5f * th); s = sinf(0.5f * th);
                #pragma unroll
                for (int m = 0; m < DIM; m++) {
                    const float sg = (m & mask) ? s : -s;
                    const float r = re[m], i = im[m];
                    re[m] = c * r - sg * i;
                    im[m] = c * i + sg * r;
                }
            }
            // CNOT chain: (0,1),(1,2),(2,3),(3,0)
            const int cq[4] = {0, 1, 2, 3};
            const int tq_[4] = {1, 2, 3, 0};
            #pragma unroll
            for (int e = 0; e < 4; e++) {
                const int cmask = 1 << (3 - cq[e]);
                const int tmask = 1 << (3 - tq_[e]);
                #pragma unroll
                for (int m = 0; m < DIM; m++) {
                    if ((m & cmask) && !(m & tmask)) {
                        const int m1 = m | tmask;
                        float tr = re[m]; re[m] = re[m1]; re[m1] = tr;
                        float ti = im[m]; im[m] = im[m1]; im[m1] = ti;
                    }
                }
            }
        }
        #pragma unroll
        for (int m = 0; m < DIM; m++) { Vre[k][m] = re[m]; Vim[k][m] = im[m]; }
    }
    __syncthreads();

    // Expand into the 81-term basis.
    // For basis term t (digits t_q in {0:const, 1:cos, 2:sin}), exactly 16
    // (k,l) pairs contribute, each with weight prod(+-1/2) = +-1/16.
    for (int idx = tid; idx < 4 * NT3; idx += blockDim.x) {
        const int i = idx / NT3;      // ev index (Z on qubit i)
        const int t = idx % NT3;
        const int tq[4] = { t / 27, (t / 9) % 3, (t / 3) % 3, t % 3 };

        float acc = 0.f;
        for (int b = 0; b < 16; b++) {
            int k = 0, l = 0;
            float sgn = 1.f / 16.f;
            for (int q = 0; q < 4; q++) {
                const int bq = (b >> q) & 1;
                const int sh = 3 - q;
                if (tq[q] == 2) {              // sin: off-diagonal k_q != l_q
                    k |= bq << sh; l |= (1 - bq) << sh;
                } else {                        // const/cos: diagonal k_q == l_q
                    k |= bq << sh; l |= bq << sh;
                    if (tq[q] == 1 && bq) sgn = -sgn;   // cos: +1/2 for |0>, -1/2 for |1>
                }
            }
            // Re(M_i[k,l]) = sum_m z_i(m) * Re(conj(V[m,k]) V[m,l])
            float mm = 0.f;
            for (int m = 0; m < DIM; m++) {
                const float zz = ((m >> (3 - i)) & 1) ? -1.f : 1.f;
                mm += zz * (Vre[k][m] * Vre[l][m] + Vim[k][m] * Vim[l][m]);
            }
            acc += sgn * mm;
        }
        g_C[(h * NT3 + t) * 4 + i] = acc;
    }
}

// ---------------------------------------------------------------------------
// Main kernel: one thread per token. Per head: 4 sincos, 81 basis products,
// 4x81 FMA for ev, then fold ev directly into the 32 output accumulators
// with W from shared (all shared reads are warp-uniform => broadcast).
// ---------------------------------------------------------------------------
__global__ __launch_bounds__(128) void qc_main_kernel(
    const float*  __restrict__ x,
    const float*  __restrict__ W,      // [EMB][NH*NQ] row-major
    const float*  __restrict__ bias,   // [EMB]
    float*        __restrict__ out,
    int ntok)
{
    __shared__ float4 Cs[NH * NT3];    // [h][t] -> C for i = 0..3
    __shared__ float4 Ws4[EMB * NH];   // [j][h] -> W[j][4h .. 4h+3]
    __shared__ float  bs[EMB];

    const int tid = threadIdx.x;
    for (int i = tid; i < NH * NT3; i += blockDim.x) {
        const float* g = g_C + i * 4;
        Cs[i] = make_float4(g[0], g[1], g[2], g[3]);
    }
    for (int i = tid; i < EMB * NH; i += blockDim.x) {
        // (j = i/NH, h = i%NH): W[j*32 + 4h] == W[i*4] since j*32+4h = (j*8+h)*4
        const float* w = W + i * 4;
        Ws4[i] = make_float4(w[0], w[1], w[2], w[3]);
    }
    if (tid < EMB) bs[tid] = bias[tid];
    __syncthreads();

    const int tok = blockIdx.x * blockDim.x + tid;
    if (tok >= ntok) return;

    const float4* xp = reinterpret_cast<const float4*>(x + (size_t)tok * EMB);

    float acc[EMB];
    #pragma unroll
    for (int j = 0; j < EMB; j++) acc[j] = bs[j];

    for (int h = 0; h < NH; h++) {
        const float4 xa = xp[h];
        float c0, s0, c1, s1, c2, s2, c3, s3;
        __sincosf(xa.x, &s0, &c0);
        __sincosf(xa.y, &s1, &c1);
        __sincosf(xa.z, &s2, &c2);
        __sincosf(xa.w, &s3, &c3);

        const float B0[3] = {1.f, c0, s0};
        const float B1[3] = {1.f, c1, s1};
        const float B2[3] = {1.f, c2, s2};
        const float B3[3] = {1.f, c3, s3};

        float e0 = 0.f, e1 = 0.f, e2 = 0.f, e3 = 0.f;
        const float4* Ch = Cs + h * NT3;

        #pragma unroll
        for (int t0 = 0; t0 < 3; t0++) {
            const float p0 = B0[t0];
            #pragma unroll
            for (int t1 = 0; t1 < 3; t1++) {
                const float p1 = p0 * B1[t1];
                #pragma unroll
                for (int t2 = 0; t2 < 3; t2++) {
                    const float p2 = p1 * B2[t2];
                    #pragma unroll
                    for (int t3 = 0; t3 < 3; t3++) {
                        const float ph = p2 * B3[t3];
                        const float4 cc = Ch[((t0 * 3 + t1) * 3 + t2) * 3 + t3];
                        e0 = fmaf(cc.x, ph, e0);
                        e1 = fmaf(cc.y, ph, e1);
                        e2 = fmaf(cc.z, ph, e2);
                        e3 = fmaf(cc.w, ph, e3);
                    }
                }
            }
        }

        // Fold this head's 4 ev values into all 32 outputs.
        #pragma unroll
        for (int j = 0; j < EMB; j++) {
            const float4 w = Ws4[j * NH + h];
            acc[j] = fmaf(w.x, e0, fmaf(w.y, e1, fmaf(w.z, e2, fmaf(w.w, e3, acc[j]))));
        }
    }

    float4* op = reinterpret_cast<float4*>(out + (size_t)tok * EMB);
    #pragma unroll
    for (int j = 0; j < EMB; j += 4)
        op[j >> 2] = make_float4(acc[j], acc[j + 1], acc[j + 2], acc[j + 3]);
}

// ---------------------------------------------------------------------------
extern "C" void kernel_launch(void* const* d_in, const int* in_sizes, int n_in,
                              void* d_out, int out_size) {
    const float* x      = (const float*)d_in[0];
    const float* params = (const float*)d_in[1];
    const float* W      = (const float*)d_in[2];
    const float* b      = (const float*)d_in[3];
    float* out = (float*)d_out;

    const int ntok = in_sizes[0] / EMB;

    qc_setup_kernel<<<NH, 128>>>(params);

    const int threads = 128;
    const int blocks  = (ntok + threads - 1) / threads;
    qc_main_kernel<<<blocks, threads>>>(x, W, b, out, ntok);
}

// round 2
// speedup vs baseline: 1.3774x; 1.3774x over previous
#include <cuda_runtime.h>

#define NQ   4
#define DIM  16
#define NH   8
#define NL   2
#define EMB  32
#define NT3  81   // 3^4 basis terms per head
#define TPT  4    // tokens per thread
#define BLK  128  // threads per block

// Per-head Fourier coefficients: layout [h][t][i]  (i = qubit/ev index, float4-friendly)
__device__ float g_C[NH * NT3 * 4];

// ---------------------------------------------------------------------------
// Setup kernel: simulate the fixed (param-only) unitary U_h on all 16 basis
// states, then expand ev_i = psi^T Re(U^dag Z_i U) psi into the 81-term
// {1, cos x_q, sin x_q} tensor basis.
// Phase 2 now goes through an intermediate M_i[k,l] table so the per-entry
// work is a 16-term table lookup instead of a 16x16 conflicted dot product.
// Grid: NH blocks x 128 threads.
// ---------------------------------------------------------------------------
__global__ void qc_setup_kernel(const float* __restrict__ params) {
    __shared__ float Vre[DIM][DIM + 1];   // padded: conflict-free column reads
    __shared__ float Vim[DIM][DIM + 1];
    __shared__ float Msh[DIM * DIM][4];   // M_i[k*16+l][i]

    const int h   = blockIdx.x;
    const int tid = threadIdx.x;

    // ---- Phase 1: simulate U_h on the 16 basis states (threads 0..15) ----
    if (tid < DIM) {
        const int k = tid;
        float re[DIM], im[DIM];
        #pragma unroll
        for (int m = 0; m < DIM; m++) { re[m] = 0.f; im[m] = 0.f; }
        re[k] = 1.f;

        const float* p = params + h * NL * NQ * 3;

        for (int l = 0; l < NL; l++) {
            for (int q = 0; q < NQ; q++) {
                const int mask = 1 << (3 - q);   // qubit 0 = MSB (reference layout)
                float th, c, s;

                // RX(theta)
                th = p[(l * NQ + q) * 3 + 0];
                c = cosf(0.5f * th); s = sinf(0.5f * th);
                #pragma unroll
                for (int m = 0; m < DIM; m++) {
                    if (!(m & mask)) {
                        const int m1 = m | mask;
                        float r0 = re[m], i0 = im[m], r1 = re[m1], i1 = im[m1];
                        re[m]  = c * r0 + s * i1;
                        im[m]  = c * i0 - s * r1;
                        re[m1] = c * r1 + s * i0;
                        im[m1] = c * i1 - s * r0;
                    }
                }
                // RY(theta)
                th = p[(l * NQ + q) * 3 + 1];
                c = cosf(0.5f * th); s = sinf(0.5f * th);
                #pragma unroll
                for (int m = 0; m < DIM; m++) {
                    if (!(m & mask)) {
                        const int m1 = m | mask;
                        float r0 = re[m], i0 = im[m], r1 = re[m1], i1 = im[m1];
                        re[m]  = c * r0 - s * r1;
                        im[m]  = c * i0 - s * i1;
                        re[m1] = s * r0 + c * r1;
                        im[m1] = s * i0 + c * i1;
                    }
                }
                // RZ(theta): diag(e^{-i th/2}, e^{+i th/2})
                th = p[(l * NQ + q) * 3 + 2];
                c = cosf(0.5f * th); s = sinf(0.5f * th);
                #pragma unroll
                for (int m = 0; m < DIM; m++) {
                    const float sg = (m & mask) ? s : -s;
                    const float r = re[m], i = im[m];
                    re[m] = c * r - sg * i;
                    im[m] = c * i + sg * r;
                }
            }
            // CNOT chain: (0,1),(1,2),(2,3),(3,0)
            const int cq[4]  = {0, 1, 2, 3};
            const int tq_[4] = {1, 2, 3, 0};
            #pragma unroll
            for (int e = 0; e < 4; e++) {
                const int cmask = 1 << (3 - cq[e]);
                const int tmask = 1 << (3 - tq_[e]);
                #pragma unroll
                for (int m = 0; m < DIM; m++) {
                    if ((m & cmask) && !(m & tmask)) {
                        const int m1 = m | tmask;
                        float tr = re[m]; re[m] = re[m1]; re[m1] = tr;
                        float ti = im[m]; im[m] = im[m1]; im[m1] = ti;
                    }
                }
            }
        }
        #pragma unroll
        for (int m = 0; m < DIM; m++) { Vre[k][m] = re[m]; Vim[k][m] = im[m]; }
    }
    __syncthreads();

    // ---- Phase 2a: M_i[k,l] = sum_m z_i(m) Re(conj(V[m,k]) V[m,l]) ----
    for (int pair = tid; pair < DIM * DIM; pair += blockDim.x) {
        const int k = pair >> 4;
        const int l = pair & 15;
        float P[DIM];
        float tot = 0.f;
        #pragma unroll
        for (int m = 0; m < DIM; m++) {
            P[m] = Vre[k][m] * Vre[l][m] + Vim[k][m] * Vim[l][m];
            tot += P[m];
        }
        #pragma unroll
        for (int i = 0; i < 4; i++) {
            float sub = 0.f;
            #pragma unroll
            for (int m = 0; m < DIM; m++)
                if ((m >> (3 - i)) & 1) sub += P[m];
            Msh[pair][i] = tot - 2.f * sub;
        }
    }
    __syncthreads();

    // ---- Phase 2b: expand into the 81-term basis via Msh lookups ----
    for (int idx = tid; idx < 4 * NT3; idx += blockDim.x) {
        const int i = idx / NT3;      // ev index (Z on qubit i)
        const int t = idx % NT3;
        const int tq[4] = { t / 27, (t / 9) % 3, (t / 3) % 3, t % 3 };

        float acc = 0.f;
        for (int b = 0; b < 16; b++) {
            int k = 0, l = 0;
            float sgn = 1.f / 16.f;
            #pragma unroll
            for (int q = 0; q < 4; q++) {
                const int bq = (b >> q) & 1;
                const int sh = 3 - q;
                if (tq[q] == 2) {              // sin: off-diagonal k_q != l_q
                    k |= bq << sh; l |= (1 - bq) << sh;
                } else {                        // const/cos: diagonal k_q == l_q
                    k |= bq << sh; l |= bq << sh;
                    if (tq[q] == 1 && bq) sgn = -sgn;   // cos: -1/2 for |1>
                }
            }
            acc += sgn * Msh[k * DIM + l][i];
        }
        g_C[(h * NT3 + t) * 4 + i] = acc;
    }
}

// ---------------------------------------------------------------------------
// Main kernel: 4 tokens per thread. Per head: 16 sincos, basis products,
// 4x4x81 FMA for ev, then fold ev directly into 4x32 output accumulators.
// Each broadcast LDS.128 of C/W now feeds 4 tokens (4x less L1 pressure).
// ---------------------------------------------------------------------------
__global__ __launch_bounds__(BLK) void qc_main_kernel(
    const float*  __restrict__ x,
    const float*  __restrict__ W,      // [EMB][NH*NQ] row-major
    const float*  __restrict__ bias,   // [EMB]
    float*        __restrict__ out,
    int ntok)
{
    __shared__ float4 Cs[NH * NT3];    // [h][t] -> C for i = 0..3
    __shared__ float4 Ws4[EMB * NH];   // [j][h] -> W[j][4h .. 4h+3]
    __shared__ float  bs[EMB];

    const int tid = threadIdx.x;
    for (int i = tid; i < NH * NT3; i += blockDim.x) {
        const float* g = g_C + i * 4;
        Cs[i] = make_float4(g[0], g[1], g[2], g[3]);
    }
    for (int i = tid; i < EMB * NH; i += blockDim.x) {
        const float* w = W + i * 4;    // j*32+4h == (j*8+h)*4
        Ws4[i] = make_float4(w[0], w[1], w[2], w[3]);
    }
    if (tid < EMB) bs[tid] = bias[tid];
    __syncthreads();

    const int tok0 = blockIdx.x * (BLK * TPT) + tid;  // tokens tok0 + t*BLK

    float acc[TPT][EMB];
    #pragma unroll
    for (int t = 0; t < TPT; t++)
        #pragma unroll
        for (int j = 0; j < EMB; j++) acc[t][j] = bs[j];

    const float4* xp4 = reinterpret_cast<const float4*>(x);

    #pragma unroll 1
    for (int h = 0; h < NH; h++) {
        const float4* Ch = Cs + h * NT3;

        // per-token trig basis {1, cos, sin} for the 4 qubits
        float B0[TPT][3], B1[TPT][3], B2[TPT][3], B3[TPT][3];
        #pragma unroll
        for (int t = 0; t < TPT; t++) {
            const int tok = tok0 + t * BLK;
            float4 xa = (tok < ntok) ? xp4[(size_t)tok * NH + h]
                                     : make_float4(0.f, 0.f, 0.f, 0.f);
            float c, s;
            __sincosf(xa.x, &s, &c); B0[t][0] = 1.f; B0[t][1] = c; B0[t][2] = s;
            __sincosf(xa.y, &s, &c); B1[t][0] = 1.f; B1[t][1] = c; B1[t][2] = s;
            __sincosf(xa.z, &s, &c); B2[t][0] = 1.f; B2[t][1] = c; B2[t][2] = s;
            __sincosf(xa.w, &s, &c); B3[t][0] = 1.f; B3[t][1] = c; B3[t][2] = s;
        }

        float ev[TPT][4];
        #pragma unroll
        for (int t = 0; t < TPT; t++)
            ev[t][0] = ev[t][1] = ev[t][2] = ev[t][3] = 0.f;

        #pragma unroll
        for (int a = 0; a < 3; a++) {
            float p0[TPT];
            #pragma unroll
            for (int t = 0; t < TPT; t++) p0[t] = B0[t][a];
            #pragma unroll
            for (int b = 0; b < 3; b++) {
                float p1[TPT];
                #pragma unroll
                for (int t = 0; t < TPT; t++) p1[t] = p0[t] * B1[t][b];
                #pragma unroll
                for (int c = 0; c < 3; c++) {
                    float p2[TPT];
                    #pragma unroll
                    for (int t = 0; t < TPT; t++) p2[t] = p1[t] * B2[t][c];
                    #pragma unroll
                    for (int d = 0; d < 3; d++) {
                        const float4 cc = Ch[((a * 3 + b) * 3 + c) * 3 + d];
                        #pragma unroll
                        for (int t = 0; t < TPT; t++) {
                            const float ph = p2[t] * B3[t][d];
                            ev[t][0] = fmaf(cc.x, ph, ev[t][0]);
                            ev[t][1] = fmaf(cc.y, ph, ev[t][1]);
                            ev[t][2] = fmaf(cc.z, ph, ev[t][2]);
                            ev[t][3] = fmaf(cc.w, ph, ev[t][3]);
                        }
                    }
                }
            }
        }

        // Fold this head's ev values into all 32 outputs for all 4 tokens.
        #pragma unroll
        for (int j = 0; j < EMB; j++) {
            const float4 w = Ws4[j * NH + h];
            #pragma unroll
            for (int t = 0; t < TPT; t++) {
                acc[t][j] = fmaf(w.x, ev[t][0],
                            fmaf(w.y, ev[t][1],
                            fmaf(w.z, ev[t][2],
                            fmaf(w.w, ev[t][3], acc[t][j]))));
            }
        }
    }

    #pragma unroll
    for (int t = 0; t < TPT; t++) {
        const int tok = tok0 + t * BLK;
        if (tok < ntok) {
            float4* op = reinterpret_cast<float4*>(out + (size_t)tok * EMB);
            #pragma unroll
            for (int j = 0; j < EMB; j += 4)
                op[j >> 2] = make_float4(acc[t][j], acc[t][j + 1],
                                         acc[t][j + 2], acc[t][j + 3]);
        }
    }
}

// ---------------------------------------------------------------------------
extern "C" void kernel_launch(void* const* d_in, const int* in_sizes, int n_in,
                              void* d_out, int out_size) {
    const float* x      = (const float*)d_in[0];
    const float* params = (const float*)d_in[1];
    const float* W      = (const float*)d_in[2];
    const float* b      = (const float*)d_in[3];
    float* out = (float*)d_out;

    const int ntok = in_sizes[0] / EMB;

    qc_setup_kernel<<<NH, 128>>>(params);

    const int tok_per_block = BLK * TPT;
    const int blocks = (ntok + tok_per_block - 1) / tok_per_block;
    qc_main_kernel<<<blocks, BLK>>>(x, W, b, out, ntok);
}

// round 3
// speedup vs baseline: 1.5699x; 1.1397x over previous
#include <cuda_runtime.h>

#define NQ   4
#define DIM  16
#define NH   8
#define NL   2
#define EMB  32
#define NT3  81   // 3^4 basis terms per head
#define TPT  2    // tokens per thread
#define BLK  128  // threads per block

typedef unsigned long long u64;

// Per-head Fourier coefficients: [h][t] -> float4 (ev index 0..3), 16B aligned
__device__ float4 g_C4[NH * NT3];

// ---- packed f32x2 helpers -------------------------------------------------
#define FMAX2(d, a, b, c) \
    asm("fma.rn.f32x2 %0, %1, %2, %3;" : "=l"(d) : "l"(a), "l"(b), "l"(c))
#define PACK2(d, lo, hi) \
    asm("mov.b64 %0, {%1, %2};" : "=l"(d) : "f"(lo), "f"(hi))
#define UNPACK2(lo, hi, d) \
    asm("mov.b64 {%0, %1}, %2;" : "=f"(lo), "=f"(hi) : "l"(d))

// ---------------------------------------------------------------------------
// Setup kernel: shuffle-parallel simulation of the fixed per-head unitary.
// 8 blocks x 256 threads; thread (k,m) holds amplitude <m|U|k>.
// Each gate: 2 shfl_xor + a few FMAs (chain depth ~30 ops total).
// Then expand ev_i = psi^T Re(U^dag Z_i U) psi into the 81-term
// {1, cos x_q, sin x_q} tensor basis via an intermediate M table.
// ---------------------------------------------------------------------------
__global__ void qc_setup_kernel(const float* __restrict__ params) {
    __shared__ float Vre[DIM][DIM + 1];
    __shared__ float Vim[DIM][DIM + 1];
    __shared__ float Msh[DIM * DIM][4];

    const int h   = blockIdx.x;
    const int tid = threadIdx.x;     // 0..255
    const int m   = tid & 15;        // amplitude index (low 4 bits of lane)
    const int k   = tid >> 4;        // input basis state

    float re = (k == m) ? 1.f : 0.f;
    float im = 0.f;

    const float* p = params + h * NL * NQ * 3;

    #pragma unroll
    for (int l = 0; l < NL; l++) {
        #pragma unroll
        for (int q = 0; q < NQ; q++) {
            const int mask = 8 >> q;   // qubit 0 = MSB
            float th, c, s, r1, i1;

            // RX: re' = c*re + s*im_p ; im' = c*im - s*re_p   (symmetric)
            th = p[(l * NQ + q) * 3 + 0];
            c = cosf(0.5f * th); s = sinf(0.5f * th);
            r1 = __shfl_xor_sync(0xffffffffu, re, mask);
            i1 = __shfl_xor_sync(0xffffffffu, im, mask);
            re = c * re + s * i1;
            im = c * im - s * r1;

            // RY: re' = c*re + sgn*re_p ; im' = c*im + sgn*im_p, sgn=+s if bit set else -s
            th = p[(l * NQ + q) * 3 + 1];
            c = cosf(0.5f * th); s = sinf(0.5f * th);
            r1 = __shfl_xor_sync(0xffffffffu, re, mask);
            i1 = __shfl_xor_sync(0xffffffffu, im, mask);
            {
                const float sgn = (m & mask) ? s : -s;
                re = c * re + sgn * r1;
                im = c * im + sgn * i1;
            }

            // RZ: diag(e^{-i th/2}, e^{+i th/2})
            th = p[(l * NQ + q) * 3 + 2];
            c = cosf(0.5f * th); s = sinf(0.5f * th);
            {
                const float sg = (m & mask) ? s : -s;
                const float r = re, i = im;
                re = c * r - sg * i;
                im = c * i + sg * r;
            }
        }
        // CNOT chain: (0,1),(1,2),(2,3),(3,0) -> (cmask,tmask) pairs
        const int cm[4] = {8, 4, 2, 1};
        const int tm[4] = {4, 2, 1, 8};
        #pragma unroll
        for (int e = 0; e < 4; e++) {
            const float r1 = __shfl_xor_sync(0xffffffffu, re, tm[e]);
            const float i1 = __shfl_xor_sync(0xffffffffu, im, tm[e]);
            if (m & cm[e]) { re = r1; im = i1; }
        }
    }

    Vre[k][m] = re;
    Vim[k][m] = im;
    __syncthreads();

    // M_i[k,l] = sum_m z_i(m) Re(conj(V[m,k]) V[m,l]); one (k,l) pair per thread
    {
        const int kk = tid >> 4;
        const int ll = tid & 15;
        float P[DIM];
        float tot = 0.f;
        #pragma unroll
        for (int mm = 0; mm < DIM; mm++) {
            P[mm] = Vre[kk][mm] * Vre[ll][mm] + Vim[kk][mm] * Vim[ll][mm];
            tot += P[mm];
        }
        #pragma unroll
        for (int i = 0; i < 4; i++) {
            float sub = 0.f;
            #pragma unroll
            for (int mm = 0; mm < DIM; mm++)
                if ((mm >> (3 - i)) & 1) sub += P[mm];
            Msh[tid][i] = tot - 2.f * sub;
        }
    }
    __syncthreads();

    // Expand into the 81-term basis via Msh lookups.
    for (int idx = tid; idx < 4 * NT3; idx += blockDim.x) {
        const int i = idx / NT3;
        const int t = idx % NT3;
        const int tq[4] = { t / 27, (t / 9) % 3, (t / 3) % 3, t % 3 };

        float acc = 0.f;
        for (int b = 0; b < 16; b++) {
            int kk = 0, ll = 0;
            float sgn = 1.f / 16.f;
            #pragma unroll
            for (int q = 0; q < 4; q++) {
                const int bq = (b >> q) & 1;
                const int sh = 3 - q;
                if (tq[q] == 2) {            // sin: off-diagonal
                    kk |= bq << sh; ll |= (1 - bq) << sh;
                } else {                     // const/cos: diagonal
                    kk |= bq << sh; ll |= bq << sh;
                    if (tq[q] == 1 && bq) sgn = -sgn;
                }
            }
            acc += sgn * Msh[kk * DIM + ll][i];
        }
        ((float*)g_C4)[(h * NT3 + t) * 4 + i] = acc;
    }
}

// ---------------------------------------------------------------------------
// Main kernel: 2 tokens/thread, packed f32x2 math.
// ev accumulation packs over ev-index pairs: the LDS.128 coefficient load
// already provides the two 64-bit halves, so only the trig product needs a
// 1-mov duplicate per (term, token).
// Output fold packs over j-pairs with a pre-transposed W layout.
// ---------------------------------------------------------------------------
__global__ __launch_bounds__(BLK) void qc_main_kernel(
    const float*  __restrict__ x,
    const float*  __restrict__ W,      // [EMB][NH*NQ] row-major
    const float*  __restrict__ bias,   // [EMB]
    float*        __restrict__ out,
    int ntok)
{
    __shared__ ulonglong2 Cs[NH * NT3];      // (c0,c1),(c2,c3) packed pairs
    __shared__ u64        Wp[NH * 4 * 16];   // [h][k][jp] = (W[2jp][4h+k], W[2jp+1][4h+k])
    __shared__ u64        bs2[16];           // (b[2jp], b[2jp+1])

    const int tid = threadIdx.x;
    for (int i = tid; i < NH * NT3; i += BLK)
        Cs[i] = reinterpret_cast<const ulonglong2*>(g_C4)[i];
    for (int i = tid; i < NH * 4 * 16; i += BLK) {
        const int jp = i & 15;
        const int kk = (i >> 4) & 3;
        const int hh = i >> 6;
        u64 v;
        PACK2(v, W[(2 * jp) * EMB + 4 * hh + kk], W[(2 * jp + 1) * EMB + 4 * hh + kk]);
        Wp[i] = v;
    }
    if (tid < 16) {
        u64 v;
        PACK2(v, bias[2 * tid], bias[2 * tid + 1]);
        bs2[tid] = v;
    }
    __syncthreads();

    const int tokA = blockIdx.x * (BLK * TPT) + tid;
    const int tokB = tokA + BLK;
    const bool okA = tokA < ntok, okB = tokB < ntok;

    u64 accA[16], accB[16];
    #pragma unroll
    for (int jp = 0; jp < 16; jp++) { accA[jp] = bs2[jp]; accB[jp] = bs2[jp]; }

    const float4* xp4 = reinterpret_cast<const float4*>(x);

    #pragma unroll 1
    for (int h = 0; h < NH; h++) {
        const ulonglong2* Ch = Cs + h * NT3;

        float4 xa = okA ? xp4[(size_t)tokA * NH + h] : make_float4(0.f, 0.f, 0.f, 0.f);
        float4 xb = okB ? xp4[(size_t)tokB * NH + h] : make_float4(0.f, 0.f, 0.f, 0.f);

        float A0[3], A1[3], A2[3], A3[3];
        float B0[3], B1[3], B2[3], B3[3];
        {
            float c, s;
            __sincosf(xa.x, &s, &c); A0[0] = 1.f; A0[1] = c; A0[2] = s;
            __sincosf(xa.y, &s, &c); A1[0] = 1.f; A1[1] = c; A1[2] = s;
            __sincosf(xa.z, &s, &c); A2[0] = 1.f; A2[1] = c; A2[2] = s;
            __sincosf(xa.w, &s, &c); A3[0] = 1.f; A3[1] = c; A3[2] = s;
            __sincosf(xb.x, &s, &c); B0[0] = 1.f; B0[1] = c; B0[2] = s;
            __sincosf(xb.y, &s, &c); B1[0] = 1.f; B1[1] = c; B1[2] = s;
            __sincosf(xb.z, &s, &c); B2[0] = 1.f; B2[1] = c; B2[2] = s;
            __sincosf(xb.w, &s, &c); B3[0] = 1.f; B3[1] = c; B3[2] = s;
        }

        u64 evA0 = 0ull, evA1 = 0ull, evB0 = 0ull, evB1 = 0ull;  // (e0,e1),(e2,e3)

        #pragma unroll
        for (int a = 0; a < 3; a++) {
            #pragma unroll
            for (int b = 0; b < 3; b++) {
                const float q1a = A0[a] * A1[b];
                const float q1b = B0[a] * B1[b];
                #pragma unroll
                for (int c = 0; c < 3; c++) {
                    const float q2a = q1a * A2[c];
                    const float q2b = q1b * B2[c];
                    #pragma unroll
                    for (int d = 0; d < 3; d++) {
                        const float pha = q2a * A3[d];
                        const float phb = q2b * B3[d];
                        const ulonglong2 cc = Ch[((a * 3 + b) * 3 + c) * 3 + d];
                        u64 pa, pb;
                        PACK2(pa, pha, pha);
                        PACK2(pb, phb, phb);
                        FMAX2(evA0, cc.x, pa, evA0);
                        FMAX2(evA1, cc.y, pa, evA1);
                        FMAX2(evB0, cc.x, pb, evB0);
                        FMAX2(evB1, cc.y, pb, evB1);
                    }
                }
            }
        }

        // Fold: acc[j-pair] += dup(ev_k) * Wp[h][k][jp]
        float e0, e1, e2, e3;
        u64 d0, d1, d2, d3;
        const u64* Wh = Wp + h * 64;

        UNPACK2(e0, e1, evA0); UNPACK2(e2, e3, evA1);
        PACK2(d0, e0, e0); PACK2(d1, e1, e1); PACK2(d2, e2, e2); PACK2(d3, e3, e3);
        #pragma unroll
        for (int jp = 0; jp < 16; jp++) {
            FMAX2(accA[jp], Wh[jp],      d0, accA[jp]);
            FMAX2(accA[jp], Wh[16 + jp], d1, accA[jp]);
            FMAX2(accA[jp], Wh[32 + jp], d2, accA[jp]);
            FMAX2(accA[jp], Wh[48 + jp], d3, accA[jp]);
        }

        UNPACK2(e0, e1, evB0); UNPACK2(e2, e3, evB1);
        PACK2(d0, e0, e0); PACK2(d1, e1, e1); PACK2(d2, e2, e2); PACK2(d3, e3, e3);
        #pragma unroll
        for (int jp = 0; jp < 16; jp++) {
            FMAX2(accB[jp], Wh[jp],      d0, accB[jp]);
            FMAX2(accB[jp], Wh[16 + jp], d1, accB[jp]);
            FMAX2(accB[jp], Wh[32 + jp], d2, accB[jp]);
            FMAX2(accB[jp], Wh[48 + jp], d3, accB[jp]);
        }
    }

    if (okA) {
        ulonglong2* op = reinterpret_cast<ulonglong2*>(out + (size_t)tokA * EMB);
        #pragma unroll
        for (int jj = 0; jj < 8; jj++)
            op[jj] = make_ulonglong2(accA[2 * jj], accA[2 * jj + 1]);
    }
    if (okB) {
        ulonglong2* op = reinterpret_cast<ulonglong2*>(out + (size_t)tokB * EMB);
        #pragma unroll
        for (int jj = 0; jj < 8; jj++)
            op[jj] = make_ulonglong2(accB[2 * jj], accB[2 * jj + 1]);
    }
}

// ---------------------------------------------------------------------------
extern "C" void kernel_launch(void* const* d_in, const int* in_sizes, int n_in,
                              void* d_out, int out_size) {
    const float* x      = (const float*)d_in[0];
    const float* params = (const float*)d_in[1];
    const float* W      = (const float*)d_in[2];
    const float* b      = (const float*)d_in[3];
    float* out = (float*)d_out;

    const int ntok = in_sizes[0] / EMB;

    qc_setup_kernel<<<NH, 256>>>(params);

    const int tok_per_block = BLK * TPT;
    const int blocks = (ntok + tok_per_block - 1) / tok_per_block;
    qc_main_kernel<<<blocks, BLK>>>(x, W, b, out, ntok);
}